// round 12
// baseline (speedup 1.0000x reference)
#include <cuda_runtime.h>
#include <cstdint>
#include <math.h>

// YOLO post-process: decode(+select) -> per-class top-256 -> NMS -> per-image top-100.
#define NB 8
#define NC 80
#define NPTS 25200
#define KTOP 256
#define MAXB 100
#define NMS_T 0.6f
#define CAP 4096
#define ECAP 2048
#define FCAP 2048
#define K0_16 0x4000u            // key16 threshold: d <= ~2.0 (score >= ~0.5), ~2040 hits/row
#define K0_32 0x4000FFFFu        // same threshold as full-bits compare

typedef unsigned long long u64;

// ---------------- scratch (static device globals; no allocation) ----------------
__device__ float4 g_boxes4[NB * NPTS];                 // [B][N] yxyx
__device__ int g_cnt[NB * NC];                         // per-(b,c) candidate count (self-resetting)
__device__ unsigned g_cand[(size_t)NB * NC * CAP];     // [B][C][CAP] packed (key16<<15 | idx)
__device__ float4 g_cand_boxes4[NB * NC * KTOP];       // [B][C][K]
__device__ float  g_kept[NB * NC * KTOP];              // [B][C][K]

__constant__ float c_anch[3][3][2] = {
    {{12.0f/640.0f, 16.0f/640.0f}, {19.0f/640.0f, 36.0f/640.0f}, {40.0f/640.0f, 28.0f/640.0f}},
    {{36.0f/640.0f, 75.0f/640.0f}, {76.0f/640.0f, 55.0f/640.0f}, {72.0f/640.0f, 146.0f/640.0f}},
    {{142.0f/640.0f,110.0f/640.0f},{192.0f/640.0f,243.0f/640.0f},{459.0f/640.0f,401.0f/640.0f}}};

__device__ __forceinline__ float sigm(float x) { return 1.0f / (1.0f + expf(-x)); }

// Schraudolph-style approx of e^{-x}: monotone, one-sided OVERestimate (<= +6.07% rel).
__device__ __forceinline__ float approx_em(float x) {
    float y = fmaf(x, -12102203.0f, 1065353216.0f);
    y = fminf(fmaxf(y, 0.0f), 2130706432.0f);    // clamp to [0, 0x7F000000]
    return __int_as_float((int)y);
}

// ---------------- Stage 1: decode + candidate push ----------------
__global__ __launch_bounds__(256) void decode_kernel(
    const float* __restrict__ x3, const float* __restrict__ x4, const float* __restrict__ x5)
{
    __shared__ float sIn[6800];
    __shared__ float sEo1[80];          // 1 + approx e^{-obj}

    int blk = blockIdx.x;
    int b = blk / 315;
    int t = blk - b * 315;
    const float* src; int W, lvlOff, tloc, lvl;
    if (t < 240)      { lvl = 0; W = 80; lvlOff = 0;     tloc = t;       src = x3; }
    else if (t < 300) { lvl = 1; W = 40; lvlOff = 19200; tloc = t - 240; src = x4; }
    else              { lvl = 2; W = 20; lvlOff = 24000; tloc = t - 300; src = x5; }

    int tid = threadIdx.x;
    const float4* base4 = (const float4*)(src + (size_t)b * W * W * 255 + (size_t)tloc * 6800);
    for (int i = tid; i < 1700; i += 256) ((float4*)sIn)[i] = base4[i];
    __syncthreads();

    float invW = 1.0f / (float)W;
    int nGlobBase = lvlOff + tloc * 80;

    if (tid < 80) {
        const float* d = &sIn[tid * 85];
        int nLoc = tloc * 80 + tid;
        int a = nLoc % 3;
        int cell = nLoc / 3;
        int wq = cell % W;
        int hq = cell / W;
        float xc = (sigm(d[0]) + (float)wq) * invW;
        float yc = (sigm(d[1]) + (float)hq) * invW;
        float bw = expf(d[2]) * c_anch[lvl][a][0];
        float bh = expf(d[3]) * c_anch[lvl][a][1];
        float4 bx;
        bx.x = yc - bh * 0.5f;
        bx.y = xc - bw * 0.5f;
        bx.z = yc + bh * 0.5f;
        bx.w = xc + bw * 0.5f;
        g_boxes4[(size_t)b * NPTS + nGlobBase + tid] = bx;
        sEo1[tid] = 1.0f + approx_em(d[4]);
    }
    __syncthreads();

    if (tid < 160) {
        int q = tid % 20, cg = tid / 20;
        int a0 = q * 4;
        float e0 = sEo1[a0], e1 = sEo1[a0 + 1], e2 = sEo1[a0 + 2], e3 = sEo1[a0 + 3];
        const float* p = &sIn[a0 * 85 + 5 + cg];
        int bcls0 = b * NC + cg;
        unsigned nA = (unsigned)(nGlobBase + a0);
        #pragma unroll 2
        for (int j = 0; j < 10; j++) {
            // key d = (1+e^-c)(1+e^-o) = eo1 + e^-c * eo1 ; monotone inverse of score
            float dv0 = fmaf(approx_em(p[0]),   e0, e0);
            float dv1 = fmaf(approx_em(p[85]),  e1, e1);
            float dv2 = fmaf(approx_em(p[170]), e2, e2);
            float dv3 = fmaf(approx_em(p[255]), e3, e3);
            int bcls = bcls0 + 8 * j;
            unsigned bb;
            bb = __float_as_uint(dv0);
            if (bb <= K0_32) { int pp = atomicAdd(&g_cnt[bcls], 1); if (pp < CAP) g_cand[(size_t)bcls * CAP + pp] = ((bb >> 16) << 15) | nA; }
            bb = __float_as_uint(dv1);
            if (bb <= K0_32) { int pp = atomicAdd(&g_cnt[bcls], 1); if (pp < CAP) g_cand[(size_t)bcls * CAP + pp] = ((bb >> 16) << 15) | (nA + 1u); }
            bb = __float_as_uint(dv2);
            if (bb <= K0_32) { int pp = atomicAdd(&g_cnt[bcls], 1); if (pp < CAP) g_cand[(size_t)bcls * CAP + pp] = ((bb >> 16) << 15) | (nA + 2u); }
            bb = __float_as_uint(dv3);
            if (bb <= K0_32) { int pp = atomicAdd(&g_cnt[bcls], 1); if (pp < CAP) g_cand[(size_t)bcls * CAP + pp] = ((bb >> 16) << 15) | (nA + 3u); }
            p += 8;
        }
    }
}

// ---------------- helpers ----------------
template <int NW>
__device__ __forceinline__ int blockSum(int v, int* red, int tid) {
    v += __shfl_down_sync(0xffffffffu, v, 16);
    v += __shfl_down_sync(0xffffffffu, v, 8);
    v += __shfl_down_sync(0xffffffffu, v, 4);
    v += __shfl_down_sync(0xffffffffu, v, 2);
    v += __shfl_down_sync(0xffffffffu, v, 1);
    __syncthreads();
    if ((tid & 31) == 0) red[tid >> 5] = v;
    __syncthreads();
    int s = 0;
    #pragma unroll
    for (int w = 0; w < NW; w++) s += red[w];
    return s;
}

__device__ __forceinline__ const float* row_ptr(
    int b, int n,
    const float* __restrict__ x3, const float* __restrict__ x4, const float* __restrict__ x5)
{
    if (n < 19200)      return x3 + (size_t)b * 1632000 + (size_t)n * 85;
    else if (n < 24000) return x4 + (size_t)b * 408000  + (size_t)(n - 19200) * 85;
    else                return x5 + (size_t)b * 102000  + (size_t)(n - 24000) * 85;
}

__device__ __forceinline__ u64 exact_key(
    int b, int c, int n,
    const float* __restrict__ x3, const float* __restrict__ x4, const float* __restrict__ x5)
{
    const float* s = row_ptr(b, n, x3, x4, x5);
    float sc = sigm(s[5 + c]) * sigm(s[4]);
    return ((u64)__float_as_uint(sc) << 32) | (unsigned)(~(unsigned)n);
}

// on-the-fly approx key16 (bit-identical to decode's computation) — fallback only
__device__ __forceinline__ unsigned fly_key16(
    int b, int c, int n,
    const float* __restrict__ x3, const float* __restrict__ x4, const float* __restrict__ x5)
{
    const float* s = row_ptr(b, n, x3, x4, x5);
    float eo1 = 1.0f + approx_em(s[4]);
    float d = fmaf(approx_em(s[5 + c]), eo1, eo1);
    return __float_as_uint(d) >> 16;
}

// bitonic keep rule: up = ((i & k)==0); lower = element is lower index of the pair
__device__ __forceinline__ u64 btn_keep(u64 a, u64 b, bool up, bool lower) {
    u64 mx = a > b ? a : b;
    u64 mn = a > b ? b : a;
    return (up == lower) ? mx : mn;
}

__device__ __forceinline__ unsigned margin16(unsigned T0) {
    // bucket upper edge scaled by the one-sided approx-error margin (needs 1.134; use 1.15)
    unsigned Tm = __float_as_uint(__uint_as_float((T0 + 1u) << 16) * 1.15f) >> 16;
    return Tm > 0x7FFFu ? 0x7FFFu : Tm;
}

// ---------------- Stage 2: tail (find_A + rescore + exact trim + sort(512) + NMS) ----------------
// smem map: cnd u32[4096] @0 (16KB) | kE u64[2048] @16384 (16KB) | kX u64[512] @32768 (4KB)
//           red @36864 | sInts @36992
// overlays:  smask[256][8] @0 (on cnd) ; sbox float4[256] @16384 (on kE)
#define TK_SMEM 37056

__global__ __launch_bounds__(256) void topk_nms_kernel(
    const float* __restrict__ x3, const float* __restrict__ x4, const float* __restrict__ x5)
{
    extern __shared__ char sm[];
    unsigned* cnd  = (unsigned*)sm;
    u64* kE        = (u64*)(sm + 16384);
    u64* kX        = (u64*)(sm + 32768);
    int* red       = (int*)(sm + 36864);
    int* sInts     = (int*)(sm + 36992);
    unsigned* smask = (unsigned*)sm;           // overlay on cnd
    float4* sbox    = (float4*)(sm + 16384);   // overlay on kE (after trim)

    int bc = blockIdx.x;
    int tid = threadIdx.x;
    int b = bc / NC;
    int c = bc - b * NC;

    // minimal A with count(key <= A) >= KTOP among collected candidates in smem
    auto find_A = [&](int cn, unsigned Kc) -> unsigned {
        unsigned lo = 0x3F7Fu, hi = Kc;
        while (hi - lo > 1u) {
            unsigned m = (lo + hi) >> 1;
            int cl = 0;
            for (int i = tid; i < cn; i += 256) cl += ((cnd[i] >> 15) <= m);
            cl = blockSum<8>(cl, red, tid);
            if (cl >= KTOP) hi = m; else lo = m;
        }
        return hi;
    };

    // ---- obtain candidate list ----
    int cntRaw = g_cnt[bc];
    int cnt = min(cntRaw, CAP);
    unsigned KthrEff = K0_16;
    unsigned A = K0_16;

    bool need_fb = (cntRaw < KTOP) || (cntRaw > CAP);
    if (!need_fb) {
        const unsigned* gc = g_cand + (size_t)bc * CAP;
        for (int i = tid; i < cnt; i += 256) cnd[i] = gc[i];
        __syncthreads();
        A = find_A(cnt, K0_16);
        need_fb = (margin16(A) > K0_16);        // margin band exceeds collection threshold
    }
    if (need_fb) {
        // COLD: recompute approx keys on the fly from raw logits
        auto count_fly = [&](unsigned m) -> int {
            int cl = 0;
            for (int i = tid; i < NPTS; i += 256)
                cl += (fly_key16(b, c, i, x3, x4, x5) <= m);
            return blockSum<8>(cl, red, tid);
        };
        auto collect_fly = [&](unsigned Kthr) -> int {
            __syncthreads();
            if (tid == 0) sInts[0] = 0;
            __syncthreads();
            for (int i = tid; i < NPTS; i += 256) {
                unsigned k16 = fly_key16(b, c, i, x3, x4, x5);
                if (k16 <= Kthr) {
                    int p = atomicAdd(&sInts[0], 1);
                    if (p < CAP) cnd[p] = (k16 << 15) | (unsigned)i;
                }
            }
            __syncthreads();
            return sInts[0];
        };
        unsigned flo = 0x3F7Fu, fhi = 0x7FFFu;
        while (fhi - flo > 1u) {
            unsigned m = (flo + fhi) >> 1;
            int cl = count_fly(m);
            if (cl >= KTOP) fhi = m; else flo = m;
        }
        A = fhi;
        KthrEff = margin16(fhi);
        int cr = collect_fly(KthrEff);
        if (cr > CAP) { KthrEff = fhi; cr = collect_fly(fhi); }
        cnt = min(cr, CAP);
    }
    unsigned Tsel = margin16(A);
    if (Tsel > KthrEff) Tsel = KthrEff;

    // ---- exact rescore of margin survivors into kE ----
    auto rescore = [&](unsigned Tm) -> int {
        __syncthreads();
        if (tid == 0) sInts[0] = 0;
        __syncthreads();
        for (int i = tid; i < cnt; i += 256) {
            unsigned cd = cnd[i];
            if ((cd >> 15) <= Tm) {
                int p = atomicAdd(&sInts[0], 1);
                if (p < ECAP) kE[p] = exact_key(b, c, (int)(cd & 0x7FFFu), x3, x4, x5);
            }
        }
        __syncthreads();
        return sInts[0];
    };
    int ns = rescore(Tsel);
    if (ns > ECAP) ns = rescore(A);   // strict retry: count(<=A) is a few hundred
    if (ns > ECAP) ns = ECAP;

    // ---- exact trim on 32-bit score bits: max t with count(score >= t) >= KTOP (prefer <= 448) ----
    unsigned tlo = 0, thi = 0x3F800000u;
    {
        bool done = false;
        while (!done && (thi - tlo) > 1u) {
            unsigned m = (tlo + thi) >> 1;
            int cl = 0;
            for (int i = tid; i < ns; i += 256) cl += ((unsigned)(kE[i] >> 32) >= m);
            cl = blockSum<8>(cl, red, tid);
            if (cl >= KTOP) { tlo = m; done = (cl <= 448); }
            else thi = m;
        }
    }

    // compact exact survivors into kX[512]
    __syncthreads();
    if (tid == 0) sInts[0] = 0;
    __syncthreads();
    for (int i = tid; i < ns; i += 256) {
        u64 kk = kE[i];
        if ((unsigned)(kk >> 32) >= tlo) {
            int p = atomicAdd(&sInts[0], 1);
            if (p < 512) kX[p] = kk;
        }
    }
    __syncthreads();
    int cnt2 = min(sInts[0], 512);
    for (int i = cnt2 + tid; i < 512; i += 256) kX[i] = 0ULL;
    __syncthreads();

    // hybrid register bitonic sort of 512 (desc: score desc, index asc via ~n)
    u64 e0 = kX[tid];
    u64 e1 = kX[tid + 256];
    __syncthreads();

    #pragma unroll
    for (unsigned k = 2; k <= 512; k <<= 1) {
        #pragma unroll
        for (unsigned j = k >> 1; j > 0; j >>= 1) {
            bool up0 = ((tid & k) == 0);
            bool up1 = (((tid + 256) & k) == 0);
            if (j == 256) {
                u64 a = e0, bb = e1;
                e0 = btn_keep(a, bb, up0, true);
                e1 = btn_keep(bb, a, up1, false);
            } else if (j >= 32) {
                kX[tid] = e0; kX[tid + 256] = e1;
                __syncthreads();
                u64 p0 = kX[tid ^ j];
                u64 p1 = kX[(tid + 256) ^ j];
                bool lower = ((tid & j) == 0);
                e0 = btn_keep(e0, p0, up0, lower);
                e1 = btn_keep(e1, p1, up1, lower);
                __syncthreads();
            } else {
                u64 p0 = __shfl_xor_sync(0xffffffffu, e0, j);
                u64 p1 = __shfl_xor_sync(0xffffffffu, e1, j);
                bool lower = ((tid & j) == 0);
                e0 = btn_keep(e0, p0, up0, lower);
                e1 = btn_keep(e1, p1, up1, lower);
            }
        }
    }
    // element at rank tid == e0 (cnt2 >= KTOP, so all ranks < 256 are genuine)

    // ---- NMS on the exact sorted top-256 ----
    float val = __uint_as_float((unsigned)(e0 >> 32));
    unsigned n = ~(unsigned)e0;
    float4 bb4 = g_boxes4[(size_t)b * NPTS + n];
    g_cand_boxes4[(size_t)bc * KTOP + tid] = bb4;
    sbox[tid] = bb4;
    float ar = (bb4.z - bb4.x) * (bb4.w - bb4.y);
    __syncthreads();

    unsigned m8[8];
    #pragma unroll
    for (int w = 0; w < 8; w++) m8[w] = 0;
    float y0 = bb4.x, x0 = bb4.y, y1 = bb4.z, x1 = bb4.w;
    int jstart = tid & ~31;             // warp-uniform start; predicate j>tid inside
    for (int j = jstart; j < KTOP; ++j) {
        float4 bj = sbox[j];            // broadcast LDS.128
        if (j > tid) {
            float iy = fmaxf(fminf(y1, bj.z) - fmaxf(y0, bj.x), 0.0f);
            float ix = fmaxf(fminf(x1, bj.w) - fmaxf(x0, bj.y), 0.0f);
            float inter = iy * ix;
            float arj = (bj.z - bj.x) * (bj.w - bj.y);
            float uni = ar + arj - inter;
            if (inter > NMS_T * fmaxf(uni, 1e-9f)) m8[j >> 5] |= (1u << (j & 31));
        }
    }
    #pragma unroll
    for (int w = 0; w < 8; w++) smask[tid * 8 + w] = m8[w];
    __syncthreads();

    // warp-parallel greedy suppression scan (warp 0; lane w<8 owns keep word w)
    if (tid < 32) {
        unsigned kp = 0xFFFFFFFFu;
        for (int i = 0; i < KTOP; ++i) {
            unsigned kw = __shfl_sync(0xffffffffu, kp, i >> 5);
            bool alive = (kw >> (i & 31)) & 1u;
            if (alive && tid < 8) kp &= ~smask[i * 8 + tid];
        }
        if (tid < 8) red[tid] = (int)kp;
    }
    __syncthreads();

    bool keep = ((unsigned)red[tid >> 5] >> (tid & 31)) & 1u;
    g_kept[(size_t)bc * KTOP + tid] = keep ? val : 0.0f;

    // reset this row's counter for the next launch (stream-ordered before next decode)
    if (tid == 0) g_cnt[bc] = 0;
}

// ---------------- Stage 3: per-image top-100 (counting select + exact sort) ----------------
#define F_VAL  0
#define F_KEYS 81920
#define F_RED  98304
#define F_INTS 98432
#define F_SMEM 98448

__global__ __launch_bounds__(1024) void final_kernel(float* __restrict__ out)
{
    extern __shared__ char fsm[];
    uint4* v4  = (uint4*)(fsm + F_VAL);
    u64* fkeys = (u64*)(fsm + F_KEYS);
    int* red   = (int*)(fsm + F_RED);
    int* ints  = (int*)(fsm + F_INTS);

    int b = blockIdx.x, tid = threadIdx.x;
    const uint4* row4 = (const uint4*)(g_kept + (size_t)b * NC * KTOP);

    int cpos = 0;
    for (int i = tid; i < NC * KTOP / 4; i += 1024) {
        uint4 v = row4[i];
        v4[i] = v;
        cpos += (v.x >= 1u) + (v.y >= 1u) + (v.z >= 1u) + (v.w >= 1u);
    }
    __syncthreads();
    cpos = blockSum<32>(cpos, red, tid);

    int t16 = 0;
    if (cpos >= MAXB) {
        int lo = 0, hi = 0x3F81;
        bool found = false;
        while (!found && hi - lo > 1) {
            int m = (lo + hi) >> 1;
            unsigned mb = (unsigned)m << 16;
            int cl = 0;
            for (int i = tid; i < NC * KTOP / 4; i += 1024) {
                uint4 v = v4[i];
                cl += (v.x >= mb) + (v.y >= mb) + (v.z >= mb) + (v.w >= mb);
            }
            cl = blockSum<32>(cl, red, tid);
            if (cl >= MAXB) { lo = m; found = (cl <= 256); }
            else hi = m;
        }
        t16 = lo;
    }
    unsigned Tb = (unsigned)t16 << 16;
    if (Tb < 1u) Tb = 1u;               // exclude suppressed zeros

    __syncthreads();
    if (tid == 0) { ints[0] = 0; ints[1] = 0; }
    __syncthreads();
    for (int i = tid; i < NC * KTOP / 4; i += 1024) {
        uint4 v = v4[i]; int n0 = i * 4; int p;
        if (v.x >= Tb) { p = atomicAdd(&ints[0], 1); if (p < FCAP) fkeys[p] = ((u64)v.x << 32) | (unsigned)(~(unsigned)n0); }
        if (v.y >= Tb) { p = atomicAdd(&ints[0], 1); if (p < FCAP) fkeys[p] = ((u64)v.y << 32) | (unsigned)(~(unsigned)(n0+1)); }
        if (v.z >= Tb) { p = atomicAdd(&ints[0], 1); if (p < FCAP) fkeys[p] = ((u64)v.z << 32) | (unsigned)(~(unsigned)(n0+2)); }
        if (v.w >= Tb) { p = atomicAdd(&ints[0], 1); if (p < FCAP) fkeys[p] = ((u64)v.w << 32) | (unsigned)(~(unsigned)(n0+3)); }
    }
    __syncthreads();
    int cnt = min(ints[0], FCAP);
    int S = 128; while (S < cnt) S <<= 1;
    for (int i = cnt + tid; i < S; i += 1024) fkeys[i] = 0ULL;
    __syncthreads();

    for (unsigned k = 2; k <= (unsigned)S; k <<= 1) {
        for (unsigned j = k >> 1; j > 0; j >>= 1) {
            for (unsigned i = tid; i < (unsigned)S; i += 1024) {
                unsigned l = i ^ j;
                if (l > i) {
                    u64 a = fkeys[i], bb = fkeys[l];
                    bool up = ((i & k) == 0);
                    if (up ? (a < bb) : (a > bb)) { fkeys[i] = bb; fkeys[l] = a; }
                }
            }
            __syncthreads();
        }
    }

    if (tid < MAXB) {
        u64 wk = fkeys[tid];
        float val = __uint_as_float((unsigned)(wk >> 32));
        bool valid = (wk != 0ULL) && (val > 0.0f);
        float4 bx = make_float4(0.f, 0.f, 0.f, 0.f);
        float cls = 0.0f, sc = 0.0f;
        if (valid) {
            unsigned flat = ~(unsigned)wk;
            int c = (int)(flat >> 8);
            int k2 = (int)(flat & 255);
            float4 bb = g_cand_boxes4[((size_t)b * NC + c) * KTOP + k2];
            bx.x = fminf(fmaxf(bb.x, 0.0f), 1.0f);
            bx.y = fminf(fmaxf(bb.y, 0.0f), 1.0f);
            bx.z = fminf(fmaxf(bb.z, 0.0f), 1.0f);
            bx.w = fminf(fmaxf(bb.w, 0.0f), 1.0f);
            cls = (float)c;
            sc = val;
            atomicAdd(&ints[1], 1);
        }
        ((float4*)out)[b * MAXB + tid] = bx;                 // nb
        out[NB * 400 + b * MAXB + tid] = cls;                // nc
        out[NB * 500 + b * MAXB + tid] = sc;                 // ns
    }
    __syncthreads();
    if (tid == 0) out[NB * 600 + b] = (float)ints[1];        // num_detections
}

// ---------------- launch ----------------
extern "C" void kernel_launch(void* const* d_in, const int* in_sizes, int n_in,
                              void* d_out, int out_size)
{
    const float* x3 = (const float*)d_in[0];
    const float* x4 = (const float*)d_in[1];
    const float* x5 = (const float*)d_in[2];
    float* out = (float*)d_out;

    cudaFuncSetAttribute(topk_nms_kernel, cudaFuncAttributeMaxDynamicSharedMemorySize, TK_SMEM);
    cudaFuncSetAttribute(final_kernel, cudaFuncAttributeMaxDynamicSharedMemorySize, F_SMEM);

    decode_kernel<<<NB * 315, 256>>>(x3, x4, x5);
    topk_nms_kernel<<<NB * NC, 256, TK_SMEM>>>(x3, x4, x5);
    final_kernel<<<NB, 1024, F_SMEM>>>(out);
}

// round 14
// speedup vs baseline: 2.1353x; 2.1353x over previous
#include <cuda_runtime.h>
#include <cstdint>
#include <math.h>

// YOLO post-process pipeline: decode -> per-class top-256 -> greedy NMS -> per-image top-100.
#define NB 8
#define NC 80
#define NPTS 25200
#define KTOP 256
#define MAXB 100
#define NMS_T 0.6f
#define CAP 4096
#define ECAP 2048
#define FCAP 2048
#define KB0 128               // key8 threshold == key16 0x4000 == d <= 2.0 (score >= 0.5)

typedef unsigned long long u64;

// ---------------- scratch buffers (static device globals; no allocation) ----------------
__device__ float4 g_boxes4[NB * NPTS];                     // [B][N] yxyx
__device__ unsigned char g_key8[(size_t)NB * NC * NPTS];   // [B][C][N] approx key byte (smaller=better)
__device__ float4 g_cand_boxes4[NB * NC * KTOP];           // [B][C][K]
__device__ float  g_kept[NB * NC * KTOP];                  // [B][C][K]

__constant__ float c_anch[3][3][2] = {
    {{12.0f/640.0f, 16.0f/640.0f}, {19.0f/640.0f, 36.0f/640.0f}, {40.0f/640.0f, 28.0f/640.0f}},
    {{36.0f/640.0f, 75.0f/640.0f}, {76.0f/640.0f, 55.0f/640.0f}, {72.0f/640.0f, 146.0f/640.0f}},
    {{142.0f/640.0f,110.0f/640.0f},{192.0f/640.0f,243.0f/640.0f},{459.0f/640.0f,401.0f/640.0f}}};

__device__ __forceinline__ float sigm(float x) { return 1.0f / (1.0f + expf(-x)); }

// Schraudolph approx of e^{-x}: monotone, one-sided OVERestimate (<= +6.07% relative).
__device__ __forceinline__ float approx_em(float x) {
    float y = fmaf(x, -12102203.0f, 1065353216.0f);
    y = fminf(fmaxf(y, 0.0f), 2130706432.0f);    // clamp into [0, 0x7F000000]
    return __int_as_float((int)y);
}

// d >= 1.0 always (both factors >= 1), so bits>>16 >= 0x3F80. key8 = exact offset, sat. 255.
__device__ __forceinline__ unsigned key8_of(float d) {
    unsigned t = (__float_as_uint(d) >> 16) - 0x3F80u;
    return t > 255u ? 255u : t;
}

// ---------------- Stage 1: decode (exact boxes; approx key bytes, FMA-only) ----------------
__global__ __launch_bounds__(256) void decode_kernel(
    const float* __restrict__ x3, const float* __restrict__ x4, const float* __restrict__ x5)
{
    __shared__ float sIn[6800];
    __shared__ float sEo1[80];          // 1 + approx e^{-obj}

    int blk = blockIdx.x;
    int b = blk / 315;
    int t = blk - b * 315;
    const float* src; int W, lvlOff, tloc, lvl;
    if (t < 240)      { lvl = 0; W = 80; lvlOff = 0;     tloc = t;       src = x3; }
    else if (t < 300) { lvl = 1; W = 40; lvlOff = 19200; tloc = t - 240; src = x4; }
    else              { lvl = 2; W = 20; lvlOff = 24000; tloc = t - 300; src = x5; }

    int tid = threadIdx.x;
    const float4* base4 = (const float4*)(src + (size_t)b * W * W * 255 + (size_t)tloc * 6800);
    for (int i = tid; i < 1700; i += 256) ((float4*)sIn)[i] = base4[i];
    __syncthreads();

    int nGlobBase = lvlOff + tloc * 80;
    float invW = 1.0f / (float)W;

    if (tid < 80) {
        const float* d = &sIn[tid * 85];
        int nLoc = tloc * 80 + tid;
        int a = nLoc % 3;
        int cell = nLoc / 3;
        int wq = cell % W;
        int hq = cell / W;
        float xc = (sigm(d[0]) + (float)wq) * invW;
        float yc = (sigm(d[1]) + (float)hq) * invW;
        float bw = expf(d[2]) * c_anch[lvl][a][0];
        float bh = expf(d[3]) * c_anch[lvl][a][1];
        float4 bx;
        bx.x = yc - bh * 0.5f;
        bx.y = xc - bw * 0.5f;
        bx.z = yc + bh * 0.5f;
        bx.w = xc + bw * 0.5f;
        g_boxes4[(size_t)b * NPTS + nGlobBase + tid] = bx;
        sEo1[tid] = 1.0f + approx_em(d[4]);
    }
    __syncthreads();

    if (tid < 160) {
        int q = tid % 20, cg = tid / 20;
        int a0 = q * 4;
        float e0 = sEo1[a0], e1 = sEo1[a0 + 1], e2 = sEo1[a0 + 2], e3 = sEo1[a0 + 3];
        const float* p = &sIn[a0 * 85 + 5 + cg];
        unsigned char* gp = g_key8 + ((size_t)b * NC + cg) * NPTS + nGlobBase + a0;
        #pragma unroll 2
        for (int j = 0; j < 10; j++) {
            // d = (1+e^-c)(1+e^-o) = eo1 + e^-c * eo1 -- monotone inverse of the score
            float dv0 = fmaf(approx_em(p[0]),   e0, e0);
            float dv1 = fmaf(approx_em(p[85]),  e1, e1);
            float dv2 = fmaf(approx_em(p[170]), e2, e2);
            float dv3 = fmaf(approx_em(p[255]), e3, e3);
            unsigned packed = key8_of(dv0) | (key8_of(dv1) << 8)
                            | (key8_of(dv2) << 16) | (key8_of(dv3) << 24);
            *reinterpret_cast<unsigned*>(gp) = packed;
            p += 8;
            gp += (size_t)8 * NPTS;
        }
    }
}

// ---------------- shared helpers ----------------
template <int NW>
__device__ __forceinline__ int blockSum(int v, int* red, int tid) {
    v += __shfl_down_sync(0xffffffffu, v, 16);
    v += __shfl_down_sync(0xffffffffu, v, 8);
    v += __shfl_down_sync(0xffffffffu, v, 4);
    v += __shfl_down_sync(0xffffffffu, v, 2);
    v += __shfl_down_sync(0xffffffffu, v, 1);
    __syncthreads();
    if ((tid & 31) == 0) red[tid >> 5] = v;
    __syncthreads();
    int s = 0;
    #pragma unroll
    for (int w = 0; w < NW; w++) s += red[w];
    return s;
}

__device__ __forceinline__ const float* row_ptr(
    int b, int n,
    const float* __restrict__ x3, const float* __restrict__ x4, const float* __restrict__ x5)
{
    if (n < 19200)      return x3 + (size_t)b * 1632000 + (size_t)n * 85;
    else if (n < 24000) return x4 + (size_t)b * 408000  + (size_t)(n - 19200) * 85;
    else                return x5 + (size_t)b * 102000  + (size_t)(n - 24000) * 85;
}

__device__ __forceinline__ u64 exact_key(
    int b, int c, int n,
    const float* __restrict__ x3, const float* __restrict__ x4, const float* __restrict__ x5)
{
    const float* s = row_ptr(b, n, x3, x4, x5);
    float sc = sigm(s[5 + c]) * sigm(s[4]);
    return ((u64)__float_as_uint(sc) << 32) | (unsigned)(~(unsigned)n);
}

// on-the-fly approx key16 (same FMA math as decode) — cold fallback path only
__device__ __forceinline__ unsigned fly_key16(
    int b, int c, int n,
    const float* __restrict__ x3, const float* __restrict__ x4, const float* __restrict__ x5)
{
    const float* s = row_ptr(b, n, x3, x4, x5);
    float eo1 = 1.0f + approx_em(s[4]);
    float d = fmaf(approx_em(s[5 + c]), eo1, eo1);
    return __float_as_uint(d) >> 16;
}

// bitonic keep rule: up = ((i & k)==0); lower = element is the lower index of the pair
__device__ __forceinline__ u64 btn_keep(u64 a, u64 b, bool up, bool lower) {
    u64 mx = a > b ? a : b;
    u64 mn = a > b ? b : a;
    return (up == lower) ? mx : mn;
}

__device__ __forceinline__ unsigned margin16(unsigned T0) {
    // key16 bucket upper edge, scaled by the one-sided approx margin (needs 1.134; use 1.15)
    unsigned Tm = __float_as_uint(__uint_as_float((T0 + 1u) << 16) * 1.15f) >> 16;
    return Tm > 0x7FFFu ? 0x7FFFu : Tm;
}

// ---------------- Stage 2: byte sweep + rescore + exact trim + sort(512) + NMS ----------------
// smem: cnd u32[4096] @0 (16KB) | kE u64[2048] @16384 (16KB) | kX u64[512] @32768 (4KB)
//       red @36864 | sInts @36992
// overlays: smask[256][8] @0 on cnd ; sbox float4[256] @16384 on kE
#define TK_SMEM 37056

__global__ __launch_bounds__(256) void topk_nms_kernel(
    const float* __restrict__ x3, const float* __restrict__ x4, const float* __restrict__ x5)
{
    extern __shared__ char sm[];
    unsigned* cnd   = (unsigned*)sm;
    u64* kE         = (u64*)(sm + 16384);
    u64* kX         = (u64*)(sm + 32768);
    int* red        = (int*)(sm + 36864);
    int* sInts      = (int*)(sm + 36992);
    unsigned* smask = (unsigned*)sm;           // overlay on cnd
    float4* sbox    = (float4*)(sm + 16384);   // overlay on kE (post-trim)

    int bc = blockIdx.x;
    int tid = threadIdx.x;
    int b = bc / NC;
    int c = bc - b * NC;
    const uint4* r4 = (const uint4*)(g_key8 + (size_t)bc * NPTS);  // 16 keys per LDG.128

    // fused byte sweep: collect packed (key8<<15 | idx) for key8 <= Kthr.
    // Returns the RAW counter value (can exceed CAP; caller must handle).
    auto sweep8 = [&](unsigned Kthr) -> int {
        __syncthreads();
        if (tid == 0) sInts[0] = 0;
        __syncthreads();
        unsigned KK = Kthr * 0x01010101u;
        for (int i = tid; i < NPTS / 16; i += 256) {
            uint4 v = __ldg(&r4[i]);
            unsigned m0 = __vcmpleu4(v.x, KK);
            unsigned m1 = __vcmpleu4(v.y, KK);
            unsigned m2 = __vcmpleu4(v.z, KK);
            unsigned m3 = __vcmpleu4(v.w, KK);
            if ((m0 | m1 | m2 | m3) == 0u) continue;
            unsigned n0 = (unsigned)i * 16u;
            unsigned wv[4] = { v.x, v.y, v.z, v.w };
            unsigned wm[4] = { m0, m1, m2, m3 };
            #pragma unroll
            for (int w = 0; w < 4; w++) {
                unsigned mm = wm[w];
                while (mm) {
                    int bit = __ffs(mm) - 1;
                    int by = bit >> 3;
                    mm &= ~(0xFFu << (by << 3));
                    unsigned k8 = (wv[w] >> (by << 3)) & 0xFFu;
                    int p = atomicAdd(&sInts[0], 1);
                    if (p < CAP) cnd[p] = (k8 << 15) | (n0 + (unsigned)(w * 4 + by));
                }
            }
        }
        __syncthreads();
        return sInts[0];
    };

    // minimal A8 with count(key8 <= A8) >= KTOP among collected (== global count, no overflow)
    auto find_A8 = [&](int cn) -> int {
        int lo = -1, hi = KB0;
        while (hi - lo > 1) {
            int m = (lo + hi) >> 1;
            int cl = 0;
            for (int i = tid; i < cn; i += 256) cl += ((int)(cnd[i] >> 15) <= m);
            cl = blockSum<8>(cl, red, tid);
            if (cl >= KTOP) hi = m; else lo = m;
        }
        return hi;
    };

    int cntRaw = sweep8((unsigned)KB0);
    int cnt = min(cntRaw, CAP);
    unsigned TselCmp = 0, ACmp = 0;     // thresholds in cnd key space (key8 hot / key16 cold)

    bool need_fb = (cntRaw < KTOP) || (cntRaw > CAP);
    if (!need_fb) {
        int A8 = find_A8(cnt);
        unsigned Tm16 = margin16((unsigned)A8 + 0x3F80u);
        int Tsel8 = (int)Tm16 - 0x3F80;
        if (Tsel8 > KB0) need_fb = true;       // margin band exceeds collection threshold
        else { TselCmp = (unsigned)Tsel8; ACmp = (unsigned)A8; }
    }
    if (need_fb) {
        // COLD path: recompute approx key16 on the fly from raw logits
        auto count_fly = [&](unsigned m) -> int {
            int cl = 0;
            for (int i = tid; i < NPTS; i += 256)
                cl += (fly_key16(b, c, i, x3, x4, x5) <= m);
            return blockSum<8>(cl, red, tid);
        };
        auto collect_fly = [&](unsigned Kthr) -> int {
            __syncthreads();
            if (tid == 0) sInts[0] = 0;
            __syncthreads();
            for (int i = tid; i < NPTS; i += 256) {
                unsigned k16 = fly_key16(b, c, i, x3, x4, x5);
                if (k16 <= Kthr) {
                    int p = atomicAdd(&sInts[0], 1);
                    if (p < CAP) cnd[p] = (k16 << 15) | (unsigned)i;
                }
            }
            __syncthreads();
            return sInts[0];
        };
        unsigned flo = 0x3F7Fu, fhi = 0x7FFFu;
        while (fhi - flo > 1u) {
            unsigned m = (flo + fhi) >> 1;
            int cl = count_fly(m);
            if (cl >= KTOP) fhi = m; else flo = m;
        }
        unsigned Kc = margin16(fhi);
        int cr = collect_fly(Kc);
        if (cr > CAP) { Kc = fhi; cr = collect_fly(fhi); }
        cnt = min(cr, CAP);
        ACmp = fhi;
        TselCmp = margin16(fhi);
        if (TselCmp > Kc) TselCmp = Kc;
    }

    // exact rescore of margin survivors into kE
    auto rescore = [&](unsigned Tm) -> int {
        __syncthreads();
        if (tid == 0) sInts[0] = 0;
        __syncthreads();
        for (int i = tid; i < cnt; i += 256) {
            unsigned cd = cnd[i];
            if ((cd >> 15) <= Tm) {
                int p = atomicAdd(&sInts[0], 1);
                if (p < ECAP) kE[p] = exact_key(b, c, (int)(cd & 0x7FFFu), x3, x4, x5);
            }
        }
        __syncthreads();
        return sInts[0];
    };
    int ns = rescore(TselCmp);
    if (ns > ECAP) ns = rescore(ACmp);  // strict retry: count(<=A) is a few hundred
    if (ns > ECAP) ns = ECAP;

    // exact trim on 32-bit score bits: max t with count(score >= t) >= KTOP (prefer <= 448)
    unsigned tlo = 0, thi = 0x3F800000u;
    {
        bool done = false;
        while (!done && (thi - tlo) > 1u) {
            unsigned m = (tlo + thi) >> 1;
            int cl = 0;
            for (int i = tid; i < ns; i += 256) cl += ((unsigned)(kE[i] >> 32) >= m);
            cl = blockSum<8>(cl, red, tid);
            if (cl >= KTOP) { tlo = m; done = (cl <= 448); }
            else thi = m;
        }
    }

    // compact exact survivors into kX[512]
    __syncthreads();
    if (tid == 0) sInts[0] = 0;
    __syncthreads();
    for (int i = tid; i < ns; i += 256) {
        u64 kk = kE[i];
        if ((unsigned)(kk >> 32) >= tlo) {
            int p = atomicAdd(&sInts[0], 1);
            if (p < 512) kX[p] = kk;
        }
    }
    __syncthreads();
    int cnt2 = min(sInts[0], 512);
    for (int i = cnt2 + tid; i < 512; i += 256) kX[i] = 0ULL;
    __syncthreads();

    // hybrid register bitonic sort of 512 (desc: score desc, index asc via ~n)
    u64 e0 = kX[tid];
    u64 e1 = kX[tid + 256];
    __syncthreads();

    #pragma unroll
    for (unsigned k = 2; k <= 512; k <<= 1) {
        #pragma unroll
        for (unsigned j = k >> 1; j > 0; j >>= 1) {
            bool up0 = ((tid & k) == 0);
            bool up1 = (((tid + 256) & k) == 0);
            if (j == 256) {
                u64 a = e0, bb = e1;
                e0 = btn_keep(a, bb, up0, true);
                e1 = btn_keep(bb, a, up1, false);
            } else if (j >= 32) {
                kX[tid] = e0; kX[tid + 256] = e1;
                __syncthreads();
                u64 p0 = kX[tid ^ j];
                u64 p1 = kX[(tid + 256) ^ j];
                bool lower = ((tid & j) == 0);
                e0 = btn_keep(e0, p0, up0, lower);
                e1 = btn_keep(e1, p1, up1, lower);
                __syncthreads();
            } else {
                u64 p0 = __shfl_xor_sync(0xffffffffu, e0, j);
                u64 p1 = __shfl_xor_sync(0xffffffffu, e1, j);
                bool lower = ((tid & j) == 0);
                e0 = btn_keep(e0, p0, up0, lower);
                e1 = btn_keep(e1, p1, up1, lower);
            }
        }
    }
    // rank-tid element == e0 (cnt2 >= KTOP, so all ranks < 256 are genuine)

    // ---- NMS on the exact sorted top-256 ----
    float val = __uint_as_float((unsigned)(e0 >> 32));
    unsigned n = ~(unsigned)e0;
    float4 bb4 = g_boxes4[(size_t)b * NPTS + n];
    g_cand_boxes4[(size_t)bc * KTOP + tid] = bb4;
    sbox[tid] = bb4;
    float ar = (bb4.z - bb4.x) * (bb4.w - bb4.y);
    __syncthreads();

    unsigned m8[8];
    #pragma unroll
    for (int w = 0; w < 8; w++) m8[w] = 0;
    float y0 = bb4.x, x0 = bb4.y, y1 = bb4.z, x1 = bb4.w;
    int jstart = tid & ~31;             // warp-uniform start; j>tid predicate inside
    for (int j = jstart; j < KTOP; ++j) {
        float4 bj = sbox[j];            // broadcast LDS.128
        if (j > tid) {
            float iy = fmaxf(fminf(y1, bj.z) - fmaxf(y0, bj.x), 0.0f);
            float ix = fmaxf(fminf(x1, bj.w) - fmaxf(x0, bj.y), 0.0f);
            float inter = iy * ix;
            float arj = (bj.z - bj.x) * (bj.w - bj.y);
            float uni = ar + arj - inter;
            if (inter > NMS_T * fmaxf(uni, 1e-9f)) m8[j >> 5] |= (1u << (j & 31));
        }
    }
    #pragma unroll
    for (int w = 0; w < 8; w++) smask[tid * 8 + w] = m8[w];
    __syncthreads();

    // warp-parallel greedy suppression scan (warp 0; lane w<8 owns keep word w)
    if (tid < 32) {
        unsigned kp = 0xFFFFFFFFu;
        for (int i = 0; i < KTOP; ++i) {
            unsigned kw = __shfl_sync(0xffffffffu, kp, i >> 5);
            bool alive = (kw >> (i & 31)) & 1u;
            if (alive && tid < 8) kp &= ~smask[i * 8 + tid];
        }
        if (tid < 8) red[tid] = (int)kp;
    }
    __syncthreads();

    bool keep = ((unsigned)red[tid >> 5] >> (tid & 31)) & 1u;
    g_kept[(size_t)bc * KTOP + tid] = keep ? val : 0.0f;
}

// ---------------- Stage 3: per-image top-100 (counting select + exact sort) ----------------
#define F_VAL  0
#define F_KEYS 81920
#define F_RED  98304
#define F_INTS 98432
#define F_SMEM 98448

__global__ __launch_bounds__(1024) void final_kernel(float* __restrict__ out)
{
    extern __shared__ char fsm[];
    uint4* v4  = (uint4*)(fsm + F_VAL);
    u64* fkeys = (u64*)(fsm + F_KEYS);
    int* red   = (int*)(fsm + F_RED);
    int* ints  = (int*)(fsm + F_INTS);

    int b = blockIdx.x, tid = threadIdx.x;
    const uint4* row4 = (const uint4*)(g_kept + (size_t)b * NC * KTOP);

    int cpos = 0;
    for (int i = tid; i < NC * KTOP / 4; i += 1024) {
        uint4 v = row4[i];
        v4[i] = v;
        cpos += (v.x >= 1u) + (v.y >= 1u) + (v.z >= 1u) + (v.w >= 1u);
    }
    __syncthreads();
    cpos = blockSum<32>(cpos, red, tid);

    int t16 = 0;
    if (cpos >= MAXB) {
        int lo = 0, hi = 0x3F81;
        bool found = false;
        while (!found && hi - lo > 1) {
            int m = (lo + hi) >> 1;
            unsigned mb = (unsigned)m << 16;
            int cl = 0;
            for (int i = tid; i < NC * KTOP / 4; i += 1024) {
                uint4 v = v4[i];
                cl += (v.x >= mb) + (v.y >= mb) + (v.z >= mb) + (v.w >= mb);
            }
            cl = blockSum<32>(cl, red, tid);
            if (cl >= MAXB) { lo = m; found = (cl <= 256); }
            else hi = m;
        }
        t16 = lo;
    }
    unsigned Tb = (unsigned)t16 << 16;
    if (Tb < 1u) Tb = 1u;               // exclude suppressed zeros

    __syncthreads();
    if (tid == 0) { ints[0] = 0; ints[1] = 0; }
    __syncthreads();
    for (int i = tid; i < NC * KTOP / 4; i += 1024) {
        uint4 v = v4[i]; int n0 = i * 4; int p;
        if (v.x >= Tb) { p = atomicAdd(&ints[0], 1); if (p < FCAP) fkeys[p] = ((u64)v.x << 32) | (unsigned)(~(unsigned)n0); }
        if (v.y >= Tb) { p = atomicAdd(&ints[0], 1); if (p < FCAP) fkeys[p] = ((u64)v.y << 32) | (unsigned)(~(unsigned)(n0+1)); }
        if (v.z >= Tb) { p = atomicAdd(&ints[0], 1); if (p < FCAP) fkeys[p] = ((u64)v.z << 32) | (unsigned)(~(unsigned)(n0+2)); }
        if (v.w >= Tb) { p = atomicAdd(&ints[0], 1); if (p < FCAP) fkeys[p] = ((u64)v.w << 32) | (unsigned)(~(unsigned)(n0+3)); }
    }
    __syncthreads();
    int cnt = min(ints[0], FCAP);
    int S = 128; while (S < cnt) S <<= 1;
    for (int i = cnt + tid; i < S; i += 1024) fkeys[i] = 0ULL;
    __syncthreads();

    for (unsigned k = 2; k <= (unsigned)S; k <<= 1) {
        for (unsigned j = k >> 1; j > 0; j >>= 1) {
            for (unsigned i = tid; i < (unsigned)S; i += 1024) {
                unsigned l = i ^ j;
                if (l > i) {
                    u64 a = fkeys[i], bb = fkeys[l];
                    bool up = ((i & k) == 0);
                    if (up ? (a < bb) : (a > bb)) { fkeys[i] = bb; fkeys[l] = a; }
                }
            }
            __syncthreads();
        }
    }

    if (tid < MAXB) {
        u64 wk = fkeys[tid];
        float val = __uint_as_float((unsigned)(wk >> 32));
        bool valid = (wk != 0ULL) && (val > 0.0f);
        float4 bx = make_float4(0.f, 0.f, 0.f, 0.f);
        float cls = 0.0f, sc = 0.0f;
        if (valid) {
            unsigned flat = ~(unsigned)wk;
            int c = (int)(flat >> 8);
            int k2 = (int)(flat & 255);
            float4 bb = g_cand_boxes4[((size_t)b * NC + c) * KTOP + k2];
            bx.x = fminf(fmaxf(bb.x, 0.0f), 1.0f);
            bx.y = fminf(fmaxf(bb.y, 0.0f), 1.0f);
            bx.z = fminf(fmaxf(bb.z, 0.0f), 1.0f);
            bx.w = fminf(fmaxf(bb.w, 0.0f), 1.0f);
            cls = (float)c;
            sc = val;
            atomicAdd(&ints[1], 1);
        }
        ((float4*)out)[b * MAXB + tid] = bx;                 // nb
        out[NB * 400 + b * MAXB + tid] = cls;                // nc
        out[NB * 500 + b * MAXB + tid] = sc;                 // ns
    }
    __syncthreads();
    if (tid == 0) out[NB * 600 + b] = (float)ints[1];        // num_detections
}

// ---------------- host-side launch ----------------
extern "C" void kernel_launch(void* const* d_in, const int* in_sizes, int n_in,
                              void* d_out, int out_size)
{
    const float* x3 = (const float*)d_in[0];
    const float* x4 = (const float*)d_in[1];
    const float* x5 = (const float*)d_in[2];
    float* out = (float*)d_out;

    cudaFuncSetAttribute(topk_nms_kernel, cudaFuncAttributeMaxDynamicSharedMemorySize, TK_SMEM);
    cudaFuncSetAttribute(final_kernel, cudaFuncAttributeMaxDynamicSharedMemorySize, F_SMEM);

    decode_kernel<<<NB * 315, 256>>>(x3, x4, x5);
    topk_nms_kernel<<<NB * NC, 256, TK_SMEM>>>(x3, x4, x5);
    final_kernel<<<NB, 1024, F_SMEM>>>(out);
}

// round 15
// speedup vs baseline: 2.2614x; 1.0591x over previous
#include <cuda_runtime.h>
#include <cstdint>
#include <math.h>

// YOLO post-process: decode -> per-class top-256 -> greedy NMS -> per-image top-100.
#define NB 8
#define NC 80
#define NPTS 25200
#define KTOP 256
#define MAXB 100
#define NMS_T 0.6f
#define CAP 4096
#define ECAP 2048
#define FCAP 2048
#define KB0 128               // key8 threshold == key16 0x4000 == d <= 2.0 (score >= 0.5)

typedef unsigned long long u64;

// ---------------- scratch (static device globals; no allocation) ----------------
__device__ float4 g_boxes4[NB * NPTS];                     // [B][N] yxyx
__device__ unsigned char g_key8[(size_t)NB * NC * NPTS];   // [B][C][N] approx key byte (smaller=better)
__device__ float4 g_cand_boxes4[NB * NC * KTOP];           // [B][C][K]
__device__ float  g_kept[NB * NC * KTOP];                  // [B][C][K]

__constant__ float c_anch[3][3][2] = {
    {{12.0f/640.0f, 16.0f/640.0f}, {19.0f/640.0f, 36.0f/640.0f}, {40.0f/640.0f, 28.0f/640.0f}},
    {{36.0f/640.0f, 75.0f/640.0f}, {76.0f/640.0f, 55.0f/640.0f}, {72.0f/640.0f, 146.0f/640.0f}},
    {{142.0f/640.0f,110.0f/640.0f},{192.0f/640.0f,243.0f/640.0f},{459.0f/640.0f,401.0f/640.0f}}};

__device__ __forceinline__ float sigm(float x) { return 1.0f / (1.0f + expf(-x)); }

// Schraudolph approx of e^{-x}: monotone, one-sided OVERestimate (<= +6.07% rel).
__device__ __forceinline__ float approx_em(float x) {
    float y = fmaf(x, -12102203.0f, 1065353216.0f);
    y = fminf(fmaxf(y, 0.0f), 2130706432.0f);    // clamp to [0, 0x7F000000]
    return __int_as_float((int)y);
}

// d >= 1.0 always, so bits>>16 >= 0x3F80. key8 = exact offset, saturated at 255.
__device__ __forceinline__ unsigned key8_of(float d) {
    unsigned t = (__float_as_uint(d) >> 16) - 0x3F80u;
    return t > 255u ? 255u : t;
}

// ---------------- Stage 1: decode (exact boxes; approx key bytes, FMA-only) ----------------
__global__ __launch_bounds__(256) void decode_kernel(
    const float* __restrict__ x3, const float* __restrict__ x4, const float* __restrict__ x5)
{
    __shared__ float sIn[6800];
    __shared__ float sEo1[80];

    int blk = blockIdx.x;
    int b = blk / 315;
    int t = blk - b * 315;
    const float* src; int W, lvlOff, tloc, lvl;
    if (t < 240)      { lvl = 0; W = 80; lvlOff = 0;     tloc = t;       src = x3; }
    else if (t < 300) { lvl = 1; W = 40; lvlOff = 19200; tloc = t - 240; src = x4; }
    else              { lvl = 2; W = 20; lvlOff = 24000; tloc = t - 300; src = x5; }

    int tid = threadIdx.x;
    const float4* base4 = (const float4*)(src + (size_t)b * W * W * 255 + (size_t)tloc * 6800);
    for (int i = tid; i < 1700; i += 256) ((float4*)sIn)[i] = base4[i];
    __syncthreads();

    int nGlobBase = lvlOff + tloc * 80;
    float invW = 1.0f / (float)W;

    if (tid < 80) {
        const float* d = &sIn[tid * 85];
        int nLoc = tloc * 80 + tid;
        int a = nLoc % 3;
        int cell = nLoc / 3;
        int wq = cell % W;
        int hq = cell / W;
        float xc = (sigm(d[0]) + (float)wq) * invW;
        float yc = (sigm(d[1]) + (float)hq) * invW;
        float bw = expf(d[2]) * c_anch[lvl][a][0];
        float bh = expf(d[3]) * c_anch[lvl][a][1];
        float4 bx;
        bx.x = yc - bh * 0.5f;
        bx.y = xc - bw * 0.5f;
        bx.z = yc + bh * 0.5f;
        bx.w = xc + bw * 0.5f;
        g_boxes4[(size_t)b * NPTS + nGlobBase + tid] = bx;
        sEo1[tid] = 1.0f + approx_em(d[4]);
    }
    __syncthreads();

    if (tid < 160) {
        int q = tid % 20, cg = tid / 20;
        int a0 = q * 4;
        float e0 = sEo1[a0], e1 = sEo1[a0 + 1], e2 = sEo1[a0 + 2], e3 = sEo1[a0 + 3];
        const float* p = &sIn[a0 * 85 + 5 + cg];
        unsigned char* gp = g_key8 + ((size_t)b * NC + cg) * NPTS + nGlobBase + a0;
        #pragma unroll 2
        for (int j = 0; j < 10; j++) {
            float dv0 = fmaf(approx_em(p[0]),   e0, e0);
            float dv1 = fmaf(approx_em(p[85]),  e1, e1);
            float dv2 = fmaf(approx_em(p[170]), e2, e2);
            float dv3 = fmaf(approx_em(p[255]), e3, e3);
            unsigned packed = key8_of(dv0) | (key8_of(dv1) << 8)
                            | (key8_of(dv2) << 16) | (key8_of(dv3) << 24);
            *reinterpret_cast<unsigned*>(gp) = packed;
            p += 8;
            gp += (size_t)8 * NPTS;
        }
    }
}

// ---------------- helpers ----------------
template <int NW>
__device__ __forceinline__ int blockSum(int v, int* red, int tid) {
    v += __shfl_down_sync(0xffffffffu, v, 16);
    v += __shfl_down_sync(0xffffffffu, v, 8);
    v += __shfl_down_sync(0xffffffffu, v, 4);
    v += __shfl_down_sync(0xffffffffu, v, 2);
    v += __shfl_down_sync(0xffffffffu, v, 1);
    __syncthreads();
    if ((tid & 31) == 0) red[tid >> 5] = v;
    __syncthreads();
    int s = 0;
    #pragma unroll
    for (int w = 0; w < NW; w++) s += red[w];
    return s;
}

__device__ __forceinline__ const float* row_ptr(
    int b, int n,
    const float* __restrict__ x3, const float* __restrict__ x4, const float* __restrict__ x5)
{
    if (n < 19200)      return x3 + (size_t)b * 1632000 + (size_t)n * 85;
    else if (n < 24000) return x4 + (size_t)b * 408000  + (size_t)(n - 19200) * 85;
    else                return x5 + (size_t)b * 102000  + (size_t)(n - 24000) * 85;
}

__device__ __forceinline__ u64 exact_key(
    int b, int c, int n,
    const float* __restrict__ x3, const float* __restrict__ x4, const float* __restrict__ x5)
{
    const float* s = row_ptr(b, n, x3, x4, x5);
    float sc = sigm(s[5 + c]) * sigm(s[4]);
    return ((u64)__float_as_uint(sc) << 32) | (unsigned)(~(unsigned)n);
}

// on-the-fly approx key16 (same FMA math as decode) — cold fallback only
__device__ __forceinline__ unsigned fly_key16(
    int b, int c, int n,
    const float* __restrict__ x3, const float* __restrict__ x4, const float* __restrict__ x5)
{
    const float* s = row_ptr(b, n, x3, x4, x5);
    float eo1 = 1.0f + approx_em(s[4]);
    float d = fmaf(approx_em(s[5 + c]), eo1, eo1);
    return __float_as_uint(d) >> 16;
}

__device__ __forceinline__ u64 btn_keep(u64 a, u64 b, bool up, bool lower) {
    u64 mx = a > b ? a : b;
    u64 mn = a > b ? b : a;
    return (up == lower) ? mx : mn;
}

__device__ __forceinline__ unsigned margin16(unsigned T0) {
    unsigned Tm = __float_as_uint(__uint_as_float((T0 + 1u) << 16) * 1.15f) >> 16;
    return Tm > 0x7FFFu ? 0x7FFFu : Tm;
}

// ---------------- Stage 2 ----------------
// smem: cnd u32[4096]@0 (16K) | kE u64[2048]@16384 (16K) | sortBuf u64[1024]@32768 (8K; hist overlays)
//       red@40960 | ints@41024 ; overlays: smask[256][8]@0, sbox float4[256]@16384
#define TKO_SB  32768
#define TKO_RED 40960
#define TKO_INT 41024
#define TK_SMEM 41088

__global__ __launch_bounds__(256) void topk_nms_kernel(
    const float* __restrict__ x3, const float* __restrict__ x4, const float* __restrict__ x5)
{
    extern __shared__ char sm[];
    unsigned* cnd   = (unsigned*)sm;
    u64* kE         = (u64*)(sm + 16384);
    u64* sortBuf    = (u64*)(sm + TKO_SB);
    unsigned* hist  = (unsigned*)(sm + TKO_SB);     // 8*136 ints, overlays sortBuf (pre-sort)
    int* red        = (int*)(sm + TKO_RED);
    int* sInts      = (int*)(sm + TKO_INT);
    unsigned* smask = (unsigned*)sm;                // overlay on cnd
    float4* sbox    = (float4*)(sm + 16384);        // overlay on kE (post-sort)

    int bc = blockIdx.x;
    int tid = threadIdx.x;
    int lane = tid & 31;
    int b = bc / NC;
    int c = bc - b * NC;
    const uint4* r4 = (const uint4*)(g_key8 + (size_t)bc * NPTS);  // 16 keys per LDG.128

    // ---- fused sweep: warp-prefix candidate write + per-warp key8 histogram ----
    __syncthreads();
    if (tid == 0) sInts[0] = 0;
    for (int i = tid; i < 8 * 136; i += 256) hist[i] = 0;
    __syncthreads();
    {
        unsigned KK = (unsigned)KB0 * 0x01010101u;
        unsigned hb = (unsigned)(tid >> 5) * 136u;
        for (int k = 0; k < 7; k++) {               // 7*256=1792 >= 1575, uniform iterations
            int i = tid + (k << 8);
            uint4 v = make_uint4(0u, 0u, 0u, 0u);
            unsigned m0 = 0, m1 = 0, m2 = 0, m3 = 0;
            if (i < NPTS / 16) {
                v = __ldg(&r4[i]);
                m0 = __vcmpleu4(v.x, KK); m1 = __vcmpleu4(v.y, KK);
                m2 = __vcmpleu4(v.z, KK); m3 = __vcmpleu4(v.w, KK);
            }
            int h = (__popc(m0) + __popc(m1) + __popc(m2) + __popc(m3)) >> 3;
            int pre = h;
            #pragma unroll
            for (int off = 1; off < 32; off <<= 1) {
                int tt = __shfl_up_sync(0xffffffffu, pre, off);
                if (lane >= off) pre += tt;
            }
            int tot = __shfl_sync(0xffffffffu, pre, 31);
            int base = 0;
            if (lane == 31 && tot > 0) base = atomicAdd(&sInts[0], tot);
            base = __shfl_sync(0xffffffffu, base, 31);
            if (h > 0) {
                int wp = base + pre - h;
                unsigned n0 = (unsigned)i * 16u;
                unsigned wv[4] = { v.x, v.y, v.z, v.w };
                unsigned wm[4] = { m0, m1, m2, m3 };
                #pragma unroll
                for (int w = 0; w < 4; w++) {
                    unsigned mm = wm[w];
                    while (mm) {
                        int bit = __ffs(mm) - 1;
                        int by = bit >> 3;
                        mm &= ~(0xFFu << (by << 3));
                        unsigned k8 = (wv[w] >> (by << 3)) & 0xFFu;
                        if (wp < CAP) cnd[wp] = (k8 << 15) | (n0 + (unsigned)(w * 4 + by));
                        atomicAdd(&hist[hb + k8], 1u);
                        wp++;
                    }
                }
            }
        }
    }
    __syncthreads();
    int cntRaw = sInts[0];
    int cnt = min(cntRaw, CAP);
    unsigned TselCmp = 0, ACmp = 0;   // thresholds in cnd key space (key8 hot / key16 cold)

    bool need_fb = (cntRaw < KTOP) || (cntRaw > CAP);
    if (!need_fb) {
        // histogram -> A8 (first bucket with cum >= KTOP) — identical to binary search result
        if (tid <= KB0) {
            unsigned s = 0;
            #pragma unroll
            for (int w = 0; w < 8; w++) s += hist[w * 136 + tid];
            hist[tid] = s;
        }
        __syncthreads();
        if (tid == 0) {
            int cum = 0, a8 = KB0;
            for (int q = 0; q <= KB0; q++) { cum += (int)hist[q]; if (cum >= KTOP) { a8 = q; break; } }
            sInts[1] = a8;
        }
        __syncthreads();
        int A8 = sInts[1];
        unsigned Tm16 = margin16((unsigned)A8 + 0x3F80u);
        int Tsel8 = (int)Tm16 - 0x3F80;
        if (Tsel8 > KB0) need_fb = true;
        else { TselCmp = (unsigned)Tsel8; ACmp = (unsigned)A8; }
    }
    if (need_fb) {
        // COLD: recompute approx key16 on the fly from raw logits
        auto count_fly = [&](unsigned m) -> int {
            int cl = 0;
            for (int i = tid; i < NPTS; i += 256)
                cl += (fly_key16(b, c, i, x3, x4, x5) <= m);
            return blockSum<8>(cl, red, tid);
        };
        auto collect_fly = [&](unsigned Kthr) -> int {
            __syncthreads();
            if (tid == 0) sInts[0] = 0;
            __syncthreads();
            for (int i = tid; i < NPTS; i += 256) {
                unsigned k16 = fly_key16(b, c, i, x3, x4, x5);
                if (k16 <= Kthr) {
                    int p = atomicAdd(&sInts[0], 1);
                    if (p < CAP) cnd[p] = (k16 << 15) | (unsigned)i;
                }
            }
            __syncthreads();
            return sInts[0];
        };
        unsigned flo = 0x3F7Fu, fhi = 0x7FFFu;
        while (fhi - flo > 1u) {
            unsigned m = (flo + fhi) >> 1;
            int cl = count_fly(m);
            if (cl >= KTOP) fhi = m; else flo = m;
        }
        unsigned Kc = margin16(fhi);
        int cr = collect_fly(Kc);
        if (cr > CAP) { Kc = fhi; cr = collect_fly(fhi); }
        cnt = min(cr, CAP);
        ACmp = fhi;
        TselCmp = margin16(fhi);
        if (TselCmp > Kc) TselCmp = Kc;
    }

    // ---- exact rescore of margin survivors into kE (ballot-aggregated) ----
    auto rescore = [&](unsigned Tm) -> int {
        __syncthreads();
        if (tid == 0) sInts[0] = 0;
        __syncthreads();
        int iters = (cnt + 255) >> 8;
        for (int k = 0; k < iters; k++) {
            int i = tid + (k << 8);
            bool has = false; unsigned cd = 0;
            if (i < cnt) { cd = cnd[i]; has = ((cd >> 15) <= Tm); }
            u64 key = 0;
            if (has) key = exact_key(b, c, (int)(cd & 0x7FFFu), x3, x4, x5);
            unsigned ball = __ballot_sync(0xffffffffu, has);
            int nh = __popc(ball);
            int base = 0;
            if (lane == 0 && nh > 0) base = atomicAdd(&sInts[0], nh);
            base = __shfl_sync(0xffffffffu, base, 0);
            int rk = __popc(ball & ((1u << lane) - 1u));
            if (has && base + rk < ECAP) kE[base + rk] = key;
        }
        __syncthreads();
        return sInts[0];
    };
    int ns = rescore(TselCmp);
    if (ns > ECAP) ns = rescore(ACmp);
    if (ns > ECAP) ns = ECAP;

    // ---- stage into sortBuf[1024]: direct if ns<=1024, else exact trim + compact ----
    if (ns <= 1024) {
        for (int i = tid; i < 1024; i += 256) sortBuf[i] = (i < ns) ? kE[i] : 0ULL;
        __syncthreads();
    } else {
        unsigned tlo = 0, thi = 0x3F800000u;
        bool done = false;
        while (!done && (thi - tlo) > 1u) {
            unsigned m = (tlo + thi) >> 1;
            int cl = 0;
            for (int i = tid; i < ns; i += 256) cl += ((unsigned)(kE[i] >> 32) >= m);
            cl = blockSum<8>(cl, red, tid);
            if (cl >= KTOP) { tlo = m; done = (cl <= 1024); }
            else thi = m;
        }
        __syncthreads();
        if (tid == 0) sInts[0] = 0;
        __syncthreads();
        int iters = (ns + 255) >> 8;
        for (int k = 0; k < iters; k++) {
            int i = tid + (k << 8);
            bool has = false; u64 kk = 0;
            if (i < ns) { kk = kE[i]; has = ((unsigned)(kk >> 32) >= tlo); }
            unsigned ball = __ballot_sync(0xffffffffu, has);
            int nh = __popc(ball);
            int base = 0;
            if (lane == 0 && nh > 0) base = atomicAdd(&sInts[0], nh);
            base = __shfl_sync(0xffffffffu, base, 0);
            int rk = __popc(ball & ((1u << lane) - 1u));
            if (has && base + rk < 1024) sortBuf[base + rk] = kk;
        }
        __syncthreads();
        int c2 = min(sInts[0], 1024);
        for (int i = c2 + tid; i < 1024; i += 256) sortBuf[i] = 0ULL;
        __syncthreads();
    }

    // ---- hybrid register bitonic sort of 1024 (desc: score desc, index asc via ~n) ----
    u64 E0 = sortBuf[tid], E1 = sortBuf[tid + 256], E2 = sortBuf[tid + 512], E3 = sortBuf[tid + 768];
    __syncthreads();

    #pragma unroll
    for (unsigned k = 2; k <= 1024; k <<= 1) {
        #pragma unroll
        for (unsigned j = k >> 1; j > 0; j >>= 1) {
            unsigned i0 = tid, i1 = tid + 256, i2 = tid + 512, i3 = tid + 768;
            bool up0 = (i0 & k) == 0, up1 = (i1 & k) == 0;
            bool up2 = (i2 & k) == 0, up3 = (i3 & k) == 0;
            if (j == 512) {
                u64 a;
                a = E0; E0 = btn_keep(E0, E2, up0, true); E2 = btn_keep(E2, a, up2, false);
                a = E1; E1 = btn_keep(E1, E3, up1, true); E3 = btn_keep(E3, a, up3, false);
            } else if (j == 256) {
                u64 a;
                a = E0; E0 = btn_keep(E0, E1, up0, true); E1 = btn_keep(E1, a, up1, false);
                a = E2; E2 = btn_keep(E2, E3, up2, true); E3 = btn_keep(E3, a, up3, false);
            } else if (j >= 32) {
                sortBuf[i0] = E0; sortBuf[i1] = E1; sortBuf[i2] = E2; sortBuf[i3] = E3;
                __syncthreads();
                u64 p0 = sortBuf[i0 ^ j], p1 = sortBuf[i1 ^ j];
                u64 p2 = sortBuf[i2 ^ j], p3 = sortBuf[i3 ^ j];
                bool low = (tid & j) == 0;
                E0 = btn_keep(E0, p0, up0, low); E1 = btn_keep(E1, p1, up1, low);
                E2 = btn_keep(E2, p2, up2, low); E3 = btn_keep(E3, p3, up3, low);
                __syncthreads();
            } else {
                u64 p0 = __shfl_xor_sync(0xffffffffu, E0, j);
                u64 p1 = __shfl_xor_sync(0xffffffffu, E1, j);
                u64 p2 = __shfl_xor_sync(0xffffffffu, E2, j);
                u64 p3 = __shfl_xor_sync(0xffffffffu, E3, j);
                bool low = (tid & j) == 0;
                E0 = btn_keep(E0, p0, up0, low); E1 = btn_keep(E1, p1, up1, low);
                E2 = btn_keep(E2, p2, up2, low); E3 = btn_keep(E3, p3, up3, low);
            }
        }
    }
    // rank-tid element == E0 (>=256 genuine candidates guaranteed)

    // ---- NMS on the exact sorted top-256 ----
    float val = __uint_as_float((unsigned)(E0 >> 32));
    unsigned n = ~(unsigned)E0;
    float4 bb4 = g_boxes4[(size_t)b * NPTS + n];
    g_cand_boxes4[(size_t)bc * KTOP + tid] = bb4;
    sbox[tid] = bb4;
    float ar = (bb4.z - bb4.x) * (bb4.w - bb4.y);
    __syncthreads();

    unsigned m8[8];
    #pragma unroll
    for (int w = 0; w < 8; w++) m8[w] = 0;
    float y0 = bb4.x, x0 = bb4.y, y1 = bb4.z, x1 = bb4.w;
    int jstart = tid & ~31;
    for (int j = jstart; j < KTOP; ++j) {
        float4 bj = sbox[j];
        if (j > tid) {
            float iy = fmaxf(fminf(y1, bj.z) - fmaxf(y0, bj.x), 0.0f);
            float ix = fmaxf(fminf(x1, bj.w) - fmaxf(x0, bj.y), 0.0f);
            float inter = iy * ix;
            float arj = (bj.z - bj.x) * (bj.w - bj.y);
            float uni = ar + arj - inter;
            if (inter > NMS_T * fmaxf(uni, 1e-9f)) m8[j >> 5] |= (1u << (j & 31));
        }
    }
    #pragma unroll
    for (int w = 0; w < 8; w++) smask[tid * 8 + w] = m8[w];
    __syncthreads();

    if (tid < 32) {
        unsigned kp = 0xFFFFFFFFu;
        for (int i = 0; i < KTOP; ++i) {
            unsigned kw = __shfl_sync(0xffffffffu, kp, i >> 5);
            bool alive = (kw >> (i & 31)) & 1u;
            if (alive && tid < 8) kp &= ~smask[i * 8 + tid];
        }
        if (tid < 8) red[tid] = (int)kp;
    }
    __syncthreads();

    bool keep = ((unsigned)red[tid >> 5] >> (tid & 31)) & 1u;
    g_kept[(size_t)bc * KTOP + tid] = keep ? val : 0.0f;
}

// ---------------- Stage 3: per-image top-100 (2-level histogram + exact sort) ----------------
#define F_VAL  0
#define F_KEYS 81920
#define F_RED  98304
#define F_INTS 98432
#define F_SMEM 98464

__global__ __launch_bounds__(1024) void final_kernel(float* __restrict__ out)
{
    extern __shared__ char fsm[];
    uint4* v4  = (uint4*)(fsm + F_VAL);
    u64* fkeys = (u64*)(fsm + F_KEYS);
    unsigned* fh = (unsigned*)(fsm + F_KEYS);    // histogram overlay (consumed before fkeys)
    int* red   = (int*)(fsm + F_RED);
    int* ints  = (int*)(fsm + F_INTS);

    int b = blockIdx.x, tid = threadIdx.x;
    const uint4* row4 = (const uint4*)(g_kept + (size_t)b * NC * KTOP);

    int cpos = 0;
    for (int i = tid; i < NC * KTOP / 4; i += 1024) {
        uint4 v = row4[i];
        v4[i] = v;
        cpos += (v.x >= 1u) + (v.y >= 1u) + (v.z >= 1u) + (v.w >= 1u);
    }
    __syncthreads();
    cpos = blockSum<32>(cpos, red, tid);

    int t16 = 0;
    if (cpos >= MAXB) {
        // coarse: 8 copies x 64 exponent-byte bins
        for (int i = tid; i < 512; i += 1024) fh[i] = 0;
        __syncthreads();
        unsigned hb = ((unsigned)(tid >> 5) & 7u) * 64u;
        for (int i = tid; i < NC * KTOP / 4; i += 1024) {
            uint4 v = v4[i];
            if (v.x >= 1u) atomicAdd(&fh[hb + (v.x >> 24)], 1u);
            if (v.y >= 1u) atomicAdd(&fh[hb + (v.y >> 24)], 1u);
            if (v.z >= 1u) atomicAdd(&fh[hb + (v.z >> 24)], 1u);
            if (v.w >= 1u) atomicAdd(&fh[hb + (v.w >> 24)], 1u);
        }
        __syncthreads();
        if (tid < 64) {
            unsigned s = 0;
            #pragma unroll
            for (int w = 0; w < 8; w++) s += fh[w * 64 + tid];
            fh[tid] = s;
        }
        __syncthreads();
        if (tid == 0) {
            int cum = 0, cb = 0, above = 0;
            for (int q = 63; q >= 0; q--) {
                int nc2 = cum + (int)fh[q];
                if (nc2 >= MAXB) { cb = q; above = cum; break; }
                cum = nc2;
            }
            ints[2] = cb; ints[3] = above;
        }
        __syncthreads();
        unsigned CB = (unsigned)ints[2];
        int above = ints[3];
        // fine: 8 copies x 256 bins on (bits>>16)&0xFF within coarse bin CB
        for (int i = tid; i < 2048; i += 1024) fh[i] = 0;
        __syncthreads();
        unsigned hb2 = ((unsigned)(tid >> 5) & 7u) * 256u;
        for (int i = tid; i < NC * KTOP / 4; i += 1024) {
            uint4 v = v4[i];
            if (v.x >= 1u && (v.x >> 24) == CB) atomicAdd(&fh[hb2 + ((v.x >> 16) & 0xFFu)], 1u);
            if (v.y >= 1u && (v.y >> 24) == CB) atomicAdd(&fh[hb2 + ((v.y >> 16) & 0xFFu)], 1u);
            if (v.z >= 1u && (v.z >> 24) == CB) atomicAdd(&fh[hb2 + ((v.z >> 16) & 0xFFu)], 1u);
            if (v.w >= 1u && (v.w >> 24) == CB) atomicAdd(&fh[hb2 + ((v.w >> 16) & 0xFFu)], 1u);
        }
        __syncthreads();
        if (tid < 256) {
            unsigned s = 0;
            #pragma unroll
            for (int w = 0; w < 8; w++) s += fh[w * 256 + tid];
            fh[tid] = s;
        }
        __syncthreads();
        if (tid == 0) {
            int cum = above, fb = 0;
            for (int q = 255; q >= 0; q--) { cum += (int)fh[q]; if (cum >= MAXB) { fb = q; break; } }
            ints[2] = (int)((CB << 8) | (unsigned)fb);
        }
        __syncthreads();
        t16 = ints[2];
    }
    unsigned Tb = (unsigned)t16 << 16;
    if (Tb < 1u) Tb = 1u;               // exclude suppressed zeros

    __syncthreads();
    if (tid == 0) { ints[0] = 0; ints[1] = 0; }
    __syncthreads();
    for (int i = tid; i < NC * KTOP / 4; i += 1024) {
        uint4 v = v4[i]; int n0 = i * 4; int p;
        if (v.x >= Tb) { p = atomicAdd(&ints[0], 1); if (p < FCAP) fkeys[p] = ((u64)v.x << 32) | (unsigned)(~(unsigned)n0); }
        if (v.y >= Tb) { p = atomicAdd(&ints[0], 1); if (p < FCAP) fkeys[p] = ((u64)v.y << 32) | (unsigned)(~(unsigned)(n0+1)); }
        if (v.z >= Tb) { p = atomicAdd(&ints[0], 1); if (p < FCAP) fkeys[p] = ((u64)v.z << 32) | (unsigned)(~(unsigned)(n0+2)); }
        if (v.w >= Tb) { p = atomicAdd(&ints[0], 1); if (p < FCAP) fkeys[p] = ((u64)v.w << 32) | (unsigned)(~(unsigned)(n0+3)); }
    }
    __syncthreads();
    int cnt = min(ints[0], FCAP);
    int S = 128; while (S < cnt) S <<= 1;
    for (int i = cnt + tid; i < S; i += 1024) fkeys[i] = 0ULL;
    __syncthreads();

    for (unsigned k = 2; k <= (unsigned)S; k <<= 1) {
        for (unsigned j = k >> 1; j > 0; j >>= 1) {
            for (unsigned i = tid; i < (unsigned)S; i += 1024) {
                unsigned l = i ^ j;
                if (l > i) {
                    u64 a = fkeys[i], bb = fkeys[l];
                    bool up = ((i & k) == 0);
                    if (up ? (a < bb) : (a > bb)) { fkeys[i] = bb; fkeys[l] = a; }
                }
            }
            __syncthreads();
        }
    }

    if (tid < MAXB) {
        u64 wk = fkeys[tid];
        float val = __uint_as_float((unsigned)(wk >> 32));
        bool valid = (wk != 0ULL) && (val > 0.0f);
        float4 bx = make_float4(0.f, 0.f, 0.f, 0.f);
        float cls = 0.0f, sc = 0.0f;
        if (valid) {
            unsigned flat = ~(unsigned)wk;
            int c = (int)(flat >> 8);
            int k2 = (int)(flat & 255);
            float4 bb = g_cand_boxes4[((size_t)b * NC + c) * KTOP + k2];
            bx.x = fminf(fmaxf(bb.x, 0.0f), 1.0f);
            bx.y = fminf(fmaxf(bb.y, 0.0f), 1.0f);
            bx.z = fminf(fmaxf(bb.z, 0.0f), 1.0f);
            bx.w = fminf(fmaxf(bb.w, 0.0f), 1.0f);
            cls = (float)c;
            sc = val;
            atomicAdd(&ints[1], 1);
        }
        ((float4*)out)[b * MAXB + tid] = bx;                 // nb
        out[NB * 400 + b * MAXB + tid] = cls;                // nc
        out[NB * 500 + b * MAXB + tid] = sc;                 // ns
    }
    __syncthreads();
    if (tid == 0) out[NB * 600 + b] = (float)ints[1];        // num_detections
}

// ---------------- launch ----------------
extern "C" void kernel_launch(void* const* d_in, const int* in_sizes, int n_in,
                              void* d_out, int out_size)
{
    const float* x3 = (const float*)d_in[0];
    const float* x4 = (const float*)d_in[1];
    const float* x5 = (const float*)d_in[2];
    float* out = (float*)d_out;

    cudaFuncSetAttribute(topk_nms_kernel, cudaFuncAttributeMaxDynamicSharedMemorySize, TK_SMEM);
    cudaFuncSetAttribute(final_kernel, cudaFuncAttributeMaxDynamicSharedMemorySize, F_SMEM);

    decode_kernel<<<NB * 315, 256>>>(x3, x4, x5);
    topk_nms_kernel<<<NB * NC, 256, TK_SMEM>>>(x3, x4, x5);
    final_kernel<<<NB, 1024, F_SMEM>>>(out);
}